// round 7
// baseline (speedup 1.0000x reference)
#include <cuda_runtime.h>
#include <cstdint>

#define DIN  128
#define DOUT 128
#define EDIM 16
#define MAXN 50176
#define MAXE 819200
#define BN_EPS 1e-5f
#define SCAN_BLK 512
#define NWARPS (SCAN_BLK / 32)   // 16
#define MAXB1 128                // >= ceil(MAXN/SCAN_BLK) = 98

// ---------------- device scratch (static; no runtime allocation) ------------
__device__ float g_x  [MAXN * DOUT];   // feats @ W_rel^T + b_rel
__device__ float g_res[MAXN * DOUT];   // relu(feats @ W_res^T + b_res)
__device__ float g_h  [MAXN * DOUT];   // pre-BN activations
__device__ float g_ea [MAXN * EDIM];   // scatter-add of edge_attr per dst
__device__ int   g_cnt[MAXN];          // per-dst degree (histogram)
__device__ int   g_off[MAXN + 1];      // CSR offsets
__device__ int   g_cur[MAXN];          // placement cursors
__device__ int   g_csr_src[MAXE];      // src node per CSR slot
__device__ int   g_bsum[MAXB1];        // scan phase-1 block sums
__device__ int   g_boff[MAXB1];        // scan phase-2 block offsets
__device__ float g_sum  [DOUT];
__device__ float g_sumsq[DOUT];
__device__ float g_scale[DOUT];
__device__ float g_shift[DOUT];
__device__ int   g_is64;               // edge_index dtype flag

__device__ __forceinline__ void red_add_v4(float* p, float4 v) {
    asm volatile("red.global.add.v4.f32 [%0], {%1,%2,%3,%4};"
                 :: "l"(p), "f"(v.x), "f"(v.y), "f"(v.z), "f"(v.w)
                 : "memory");
}

__device__ __forceinline__ uint32_t cvt_tf32(float a) {
    uint32_t r;
    asm("cvt.rna.tf32.f32 %0, %1;" : "=r"(r) : "f"(a));
    return r;
}

__device__ __forceinline__ void mma_tf32(float* d, const uint32_t* a, const uint32_t* b) {
    asm volatile(
        "mma.sync.aligned.m16n8k8.row.col.f32.tf32.tf32.f32 "
        "{%0,%1,%2,%3}, {%4,%5,%6,%7}, {%8,%9}, {%0,%1,%2,%3};"
        : "+f"(d[0]), "+f"(d[1]), "+f"(d[2]), "+f"(d[3])
        : "r"(a[0]), "r"(a[1]), "r"(a[2]), "r"(a[3]), "r"(b[0]), "r"(b[1]));
}

// ---------------- K0: detect edge_index dtype (int64 vs int32) --------------
__global__ void k0_detect(const unsigned int* __restrict__ ei_words) {
    __shared__ int any_nz;
    if (threadIdx.x == 0) any_nz = 0;
    __syncthreads();
    int nz = 0;
    for (int i = threadIdx.x; i < 1024; i += blockDim.x)
        nz |= (ei_words[2 * i + 1] != 0u);
    if (nz) atomicOr(&any_nz, 1);
    __syncthreads();
    if (threadIdx.x == 0) g_is64 = any_nz ? 0 : 1;
}

// ---------------- K1: tf32 tensor-core node GEMMs (3xTF32 precision) --------
// CTA tile M=64 x N=64, K=128 resident. grid.y in 0..3: mat = y>>1 (0=Wrel->g_x,
// 1=Wres->relu->g_res), nhalf = y&1. 128 threads, 4 warps, warp tile 16x64.
// A fp32 in smem (hi/lo split in regs); B hi/lo tf32 in smem. Pitch 132 for
// conflict-free fragment loads.
#define K1_PITCH 132
#define K1_SMEM  (3 * 64 * K1_PITCH * 4)   // As + Bh + Bl = 101376 bytes

__global__ __launch_bounds__(128)
void k1_gemm_tf32(const float* __restrict__ feats,
                  const float* __restrict__ Wrel, const float* __restrict__ brel,
                  const float* __restrict__ Wres, const float* __restrict__ bres,
                  int N)
{
    extern __shared__ float smem[];
    float* As = smem;                      // [64][132] fp32
    float* Bh = smem + 64 * K1_PITCH;      // [64][132] tf32 hi (as float bits)
    float* Bl = Bh  + 64 * K1_PITCH;       // [64][132] tf32 lo

    const int tid  = threadIdx.x;
    const int m0   = blockIdx.x * 64;
    const int mat  = blockIdx.y >> 1;
    const int nhalf= blockIdx.y & 1;

    // side jobs: zero scratch used by later stages
    if (blockIdx.y == 0) {
        if (tid < 64 && m0 + tid < N) g_cnt[m0 + tid] = 0;
        if (blockIdx.x == 0 && tid < DOUT) { g_sum[tid] = 0.f; g_sumsq[tid] = 0.f; }
    } else if (blockIdx.y == 1) {
        for (int i = tid; i < 64 * EDIM; i += 128) {
            int n = m0 + (i >> 4);
            if (n < N) g_ea[n * EDIM + (i & 15)] = 0.f;
        }
    }

    const float* Wsel = (mat == 0) ? Wrel : Wres;
    const float* bsel = (mat == 0) ? brel : bres;
    const int nbase = nhalf * 64;

    // load A tile (64 x 128 fp32), zero-fill OOB rows
    for (int idx = tid; idx < 64 * 32; idx += 128) {
        int row = idx >> 5, c4 = idx & 31;
        int node = m0 + row;
        float4 v = (node < N) ? *(const float4*)&feats[(size_t)node * DIN + c4 * 4]
                              : make_float4(0.f, 0.f, 0.f, 0.f);
        *(float4*)&As[row * K1_PITCH + c4 * 4] = v;
    }
    // load B tile (64 x 128) and split into tf32 hi/lo
    for (int idx = tid; idx < 64 * 32; idx += 128) {
        int row = idx >> 5, c4 = idx & 31;
        float4 w = *(const float4*)&Wsel[(size_t)(nbase + row) * DIN + c4 * 4];
        float wa[4] = {w.x, w.y, w.z, w.w};
        #pragma unroll
        for (int q = 0; q < 4; q++) {
            uint32_t hb = cvt_tf32(wa[q]);
            float hf = __uint_as_float(hb);
            uint32_t lb = cvt_tf32(wa[q] - hf);
            Bh[row * K1_PITCH + c4 * 4 + q] = __uint_as_float(hb);
            Bl[row * K1_PITCH + c4 * 4 + q] = __uint_as_float(lb);
        }
    }
    __syncthreads();

    const int warp = tid >> 5, lane = tid & 31;
    const int g = lane >> 2, tig = lane & 3;
    const int ar0 = warp * 16 + g;

    float d[8][4];
    #pragma unroll
    for (int ns = 0; ns < 8; ns++)
        #pragma unroll
        for (int q = 0; q < 4; q++) d[ns][q] = 0.f;

    #pragma unroll
    for (int ks = 0; ks < 16; ks++) {
        const int k0 = ks * 8;
        float af[4];
        af[0] = As[ar0 * K1_PITCH + k0 + tig];
        af[1] = As[(ar0 + 8) * K1_PITCH + k0 + tig];
        af[2] = As[ar0 * K1_PITCH + k0 + tig + 4];
        af[3] = As[(ar0 + 8) * K1_PITCH + k0 + tig + 4];
        uint32_t ah[4], al[4];
        #pragma unroll
        for (int q = 0; q < 4; q++) {
            ah[q] = cvt_tf32(af[q]);
            al[q] = cvt_tf32(af[q] - __uint_as_float(ah[q]));
        }
        #pragma unroll
        for (int ns = 0; ns < 8; ns++) {
            const int nr = ns * 8 + g;
            uint32_t bh[2], bl[2];
            bh[0] = __float_as_uint(Bh[nr * K1_PITCH + k0 + tig]);
            bh[1] = __float_as_uint(Bh[nr * K1_PITCH + k0 + tig + 4]);
            bl[0] = __float_as_uint(Bl[nr * K1_PITCH + k0 + tig]);
            bl[1] = __float_as_uint(Bl[nr * K1_PITCH + k0 + tig + 4]);
            mma_tf32(d[ns], ah, bh);   // hi*hi
            mma_tf32(d[ns], al, bh);   // lo*hi
            mma_tf32(d[ns], ah, bl);   // hi*lo
        }
    }

    // epilogue: bias, optional relu, store
    float* out = (mat == 0) ? g_x : g_res;
    const int row0 = m0 + warp * 16 + g;
    #pragma unroll
    for (int ns = 0; ns < 8; ns++) {
        const int col = nbase + ns * 8 + tig * 2;
        float b0 = bsel[col], b1 = bsel[col + 1];
        float v0 = d[ns][0] + b0, v1 = d[ns][1] + b1;
        float v2 = d[ns][2] + b0, v3 = d[ns][3] + b1;
        if (mat == 1) {
            v0 = fmaxf(v0, 0.f); v1 = fmaxf(v1, 0.f);
            v2 = fmaxf(v2, 0.f); v3 = fmaxf(v3, 0.f);
        }
        if (row0 < N)
            *(float2*)&out[(size_t)row0 * DOUT + col] = make_float2(v0, v1);
        if (row0 + 8 < N)
            *(float2*)&out[(size_t)(row0 + 8) * DOUT + col] = make_float2(v2, v3);
    }
}

// ---------------- K2a: histogram over dst -------------------------------------
__global__ __launch_bounds__(256)
void k_hist(const void* __restrict__ ei_raw, int E)
{
    int e = blockIdx.x * blockDim.x + threadIdx.x;
    if (e >= E) return;
    int d = g_is64 ? (int)((const long long*)ei_raw)[E + e]
                   : ((const int*)ei_raw)[E + e];
    atomicAdd(&g_cnt[d], 1);
}

// ---------------- K2b: 3-phase multi-block exclusive scan --------------------
__global__ __launch_bounds__(SCAN_BLK)
void k_scan1(int N)
{
    __shared__ int wsum[NWARPS];
    int i = blockIdx.x * SCAN_BLK + threadIdx.x;
    int wid = threadIdx.x >> 5, lane = threadIdx.x & 31;
    int v = (i < N) ? g_cnt[i] : 0;
    #pragma unroll
    for (int o = 16; o > 0; o >>= 1) v += __shfl_down_sync(0xffffffffu, v, o);
    if (lane == 0) wsum[wid] = v;
    __syncthreads();
    if (wid == 0) {
        int s = (lane < NWARPS) ? wsum[lane] : 0;
        #pragma unroll
        for (int o = 16; o > 0; o >>= 1) s += __shfl_down_sync(0xffffffffu, s, o);
        if (lane == 0) g_bsum[blockIdx.x] = s;
    }
}

__global__ __launch_bounds__(MAXB1)
void k_scan2(int nb, int N)
{
    __shared__ int ps[MAXB1];
    int t = threadIdx.x;
    int v = (t < nb) ? g_bsum[t] : 0;
    ps[t] = v;
    __syncthreads();
    #pragma unroll
    for (int o = 1; o < MAXB1; o <<= 1) {
        int y = 0;
        if (t >= o) y = ps[t - o];
        __syncthreads();
        if (t >= o) ps[t] += y;
        __syncthreads();
    }
    if (t < nb) g_boff[t] = ps[t] - v;      // exclusive
    if (t == MAXB1 - 1) g_off[N] = ps[MAXB1 - 1];
}

__global__ __launch_bounds__(SCAN_BLK)
void k_scan3(int N)
{
    __shared__ int wsum[NWARPS];
    int i = blockIdx.x * SCAN_BLK + threadIdx.x;
    int wid = threadIdx.x >> 5, lane = threadIdx.x & 31;
    int v = (i < N) ? g_cnt[i] : 0;
    int x = v;
    #pragma unroll
    for (int o = 1; o < 32; o <<= 1) {
        int y = __shfl_up_sync(0xffffffffu, x, o);
        if (lane >= o) x += y;
    }
    if (lane == 31) wsum[wid] = x;
    __syncthreads();
    if (wid == 0) {
        int s = (lane < NWARPS) ? wsum[lane] : 0;
        #pragma unroll
        for (int o = 1; o < 32; o <<= 1) {
            int y = __shfl_up_sync(0xffffffffu, s, o);
            if (lane >= o) s += y;
        }
        if (lane < NWARPS) wsum[lane] = s;
    }
    __syncthreads();
    int woff = (wid > 0) ? wsum[wid - 1] : 0;
    int excl = x - v + woff + g_boff[blockIdx.x];
    if (i < N) { g_off[i] = excl; g_cur[i] = excl; }
}

// ---------------- K2c: place edges into CSR + scatter edge_attr sums ---------
__global__ __launch_bounds__(256)
void k_place(const void* __restrict__ ei_raw, const float* __restrict__ eattr, int E)
{
    int e = blockIdx.x * blockDim.x + threadIdx.x;
    if (e >= E) return;
    int s, d;
    if (g_is64) {
        const long long* p = (const long long*)ei_raw;
        s = (int)p[e]; d = (int)p[E + e];
    } else {
        const int* p = (const int*)ei_raw;
        s = p[e]; d = p[E + e];
    }
    int pos = atomicAdd(&g_cur[d], 1);
    g_csr_src[pos] = s;

    const float4* a4 = (const float4*)&eattr[(size_t)e * EDIM];
    float* dst = &g_ea[(size_t)d * EDIM];
    red_add_v4(dst + 0,  a4[0]);
    red_add_v4(dst + 4,  a4[1]);
    red_add_v4(dst + 8,  a4[2]);
    red_add_v4(dst + 12, a4[3]);
}

// ---------------- K2d: pull aggregation fused with combine + BN partials ----
__global__ __launch_bounds__(256)
void k_pull(const float* __restrict__ We, const float* __restrict__ be, int N)
{
    __shared__ float s_sum[128];
    __shared__ float s_sq[128];
    int tid = threadIdx.x;
    if (tid < 128) { s_sum[tid] = 0.f; s_sq[tid] = 0.f; }
    __syncthreads();

    int warp = tid >> 5, lane = tid & 31;
    int n = blockIdx.x * 8 + warp;

    if (n < N) {
        const int j0 = g_off[n], j1 = g_off[n + 1];
        const int c0 = lane * 4;

        float4 acc = make_float4(0.f, 0.f, 0.f, 0.f);

        int j = j0;
        for (; j + 3 < j1; j += 4) {
            int s0 = g_csr_src[j],   s1 = g_csr_src[j+1];
            int s2 = g_csr_src[j+2], s3 = g_csr_src[j+3];
            float4 x0 = *(const float4*)&g_x[(size_t)s0 * DOUT + c0];
            float4 x1 = *(const float4*)&g_x[(size_t)s1 * DOUT + c0];
            float4 x2 = *(const float4*)&g_x[(size_t)s2 * DOUT + c0];
            float4 x3 = *(const float4*)&g_x[(size_t)s3 * DOUT + c0];
            acc.x += (x0.x + x1.x) + (x2.x + x3.x);
            acc.y += (x0.y + x1.y) + (x2.y + x3.y);
            acc.z += (x0.z + x1.z) + (x2.z + x3.z);
            acc.w += (x0.w + x1.w) + (x2.w + x3.w);
        }
        for (; j < j1; j++) {
            int s0 = g_csr_src[j];
            float4 x0 = *(const float4*)&g_x[(size_t)s0 * DOUT + c0];
            acc.x += x0.x; acc.y += x0.y; acc.z += x0.z; acc.w += x0.w;
        }

        // per-dst summed edge_attr (coalesced) -> broadcast to all lanes
        float ea = (lane < EDIM) ? g_ea[(size_t)n * EDIM + lane] : 0.f;
        float eav[EDIM];
        #pragma unroll
        for (int q = 0; q < EDIM; q++) eav[q] = __shfl_sync(0xffffffffu, ea, q);

        const float deg = (float)(j1 - j0);
        float4 b = *(const float4*)&be[c0];
        float4 elin = make_float4(b.x * deg, b.y * deg, b.z * deg, b.w * deg);

        const float4* W4 = (const float4*)We;  // row c: 4 float4 chunks
        #pragma unroll
        for (int q4 = 0; q4 < 4; q4++) {
            float4 w0 = W4[(c0 + 0) * 4 + q4];
            float4 w1 = W4[(c0 + 1) * 4 + q4];
            float4 w2 = W4[(c0 + 2) * 4 + q4];
            float4 w3 = W4[(c0 + 3) * 4 + q4];
            float e0v = eav[q4 * 4 + 0], e1v = eav[q4 * 4 + 1];
            float e2v = eav[q4 * 4 + 2], e3v = eav[q4 * 4 + 3];
            elin.x += w0.x * e0v + w0.y * e1v + w0.z * e2v + w0.w * e3v;
            elin.y += w1.x * e0v + w1.y * e1v + w1.z * e2v + w1.w * e3v;
            elin.z += w2.x * e0v + w2.y * e1v + w2.z * e2v + w2.w * e3v;
            elin.w += w3.x * e0v + w3.y * e1v + w3.z * e2v + w3.w * e3v;
        }

        float4 res = *(const float4*)&g_res[(size_t)n * DOUT + c0];
        float4 h;
        h.x = fmaxf(acc.x + elin.x, 0.f) + res.x;
        h.y = fmaxf(acc.y + elin.y, 0.f) + res.y;
        h.z = fmaxf(acc.z + elin.z, 0.f) + res.z;
        h.w = fmaxf(acc.w + elin.w, 0.f) + res.w;
        *(float4*)&g_h[(size_t)n * DOUT + c0] = h;

        atomicAdd(&s_sum[c0 + 0], h.x);
        atomicAdd(&s_sum[c0 + 1], h.y);
        atomicAdd(&s_sum[c0 + 2], h.z);
        atomicAdd(&s_sum[c0 + 3], h.w);
        atomicAdd(&s_sq[c0 + 0], h.x * h.x);
        atomicAdd(&s_sq[c0 + 1], h.y * h.y);
        atomicAdd(&s_sq[c0 + 2], h.z * h.z);
        atomicAdd(&s_sq[c0 + 3], h.w * h.w);
    }

    __syncthreads();
    if (tid < 128) {
        atomicAdd(&g_sum[tid],   s_sum[tid]);
        atomicAdd(&g_sumsq[tid], s_sq[tid]);
    }
}

// ---------------- K4: finalize BN stats --------------------------------------
__global__ void k4_stats(const float* __restrict__ gamma,
                         const float* __restrict__ beta, int N)
{
    int c = threadIdx.x;
    float invN = 1.f / (float)N;
    float mean = g_sum[c] * invN;
    float var  = g_sumsq[c] * invN - mean * mean;
    float rstd = rsqrtf(var + BN_EPS);
    float sc   = gamma[c] * rstd;
    g_scale[c] = sc;
    g_shift[c] = beta[c] - mean * sc;
}

// ---------------- K5: normalize ----------------------------------------------
__global__ __launch_bounds__(256)
void k5_norm(float* __restrict__ out, int total4)
{
    int idx = blockIdx.x * blockDim.x + threadIdx.x;
    if (idx >= total4) return;
    int c4 = (idx & (DOUT / 4 - 1)) * 4;
    float4 h  = *(const float4*)&g_h[idx * 4];
    float4 sc = *(const float4*)&g_scale[c4];
    float4 sh = *(const float4*)&g_shift[c4];
    float4 o;
    o.x = h.x * sc.x + sh.x;
    o.y = h.y * sc.y + sh.y;
    o.z = h.z * sc.z + sh.z;
    o.w = h.w * sc.w + sh.w;
    ((float4*)out)[idx] = o;
}

// ---------------- launch ------------------------------------------------------
extern "C" void kernel_launch(void* const* d_in, const int* in_sizes, int n_in,
                              void* d_out, int out_size)
{
    const float* feats = (const float*)d_in[0];
    const void*  ei    = d_in[1];
    const float* eattr = (const float*)d_in[2];
    const float* Wrel  = (const float*)d_in[3];
    const float* brel  = (const float*)d_in[4];
    const float* We    = (const float*)d_in[5];
    const float* be    = (const float*)d_in[6];
    const float* Wres  = (const float*)d_in[7];
    const float* bres  = (const float*)d_in[8];
    const float* gamma = (const float*)d_in[9];
    const float* beta  = (const float*)d_in[10];

    const int N = in_sizes[0] / DIN;
    const int E = in_sizes[2] / EDIM;
    const int nb = (N + SCAN_BLK - 1) / SCAN_BLK;

    static int smem_set = 0;
    if (!smem_set) {
        cudaFuncSetAttribute(k1_gemm_tf32,
                             cudaFuncAttributeMaxDynamicSharedMemorySize, K1_SMEM);
        smem_set = 1;
    }

    k0_detect<<<1, 256>>>((const unsigned int*)ei);
    dim3 g1((N + 63) / 64, 4);
    k1_gemm_tf32<<<g1, 128, K1_SMEM>>>(feats, Wrel, brel, Wres, bres, N);
    k_hist<<<(E + 255) / 256, 256>>>(ei, E);
    k_scan1<<<nb, SCAN_BLK>>>(N);
    k_scan2<<<1, MAXB1>>>(nb, N);
    k_scan3<<<nb, SCAN_BLK>>>(N);
    k_place<<<(E + 255) / 256, 256>>>(ei, eattr, E);
    k_pull<<<(N + 7) / 8, 256>>>(We, be, N);
    k4_stats<<<1, 128>>>(gamma, beta, N);
    int total4 = N * DOUT / 4;
    k5_norm<<<(total4 + 255) / 256, 256>>>((float*)d_out, total4);
}

// round 8
// speedup vs baseline: 1.2162x; 1.2162x over previous
#include <cuda_runtime.h>
#include <cstdint>

#define DIN  128
#define DOUT 128
#define EDIM 16
#define MAXN 50176
#define MAXE 819200
#define BN_EPS 1e-5f
#define SCAN_BLK 512
#define NWARPS (SCAN_BLK / 32)   // 16
#define MAXB1 128                // >= ceil(MAXN/SCAN_BLK) = 98

// ---------------- device scratch (static; no runtime allocation) ------------
__device__ float g_x  [MAXN * DOUT];   // feats @ W_rel^T + b_rel
__device__ float g_res[MAXN * DOUT];   // relu(feats @ W_res^T + b_res)
__device__ float g_h  [MAXN * DOUT];   // pre-BN activations
__device__ float g_ea [MAXN * EDIM];   // scatter-add of edge_attr per dst
__device__ int   g_cnt[MAXN];          // per-dst degree (histogram)
__device__ int   g_off[MAXN + 1];      // CSR offsets
__device__ int   g_cur[MAXN];          // placement cursors
__device__ int   g_csr_src[MAXE];      // src node per CSR slot
__device__ int   g_bsum[MAXB1];        // scan phase-1 block sums
__device__ int   g_boff[MAXB1];        // scan phase-2 block offsets
__device__ float g_sum  [DOUT];
__device__ float g_sumsq[DOUT];
__device__ float g_scale[DOUT];
__device__ float g_shift[DOUT];
__device__ int   g_is64;               // edge_index dtype flag

__device__ __forceinline__ void red_add_v4(float* p, float4 v) {
    asm volatile("red.global.add.v4.f32 [%0], {%1,%2,%3,%4};"
                 :: "l"(p), "f"(v.x), "f"(v.y), "f"(v.z), "f"(v.w)
                 : "memory");
}

__device__ __forceinline__ uint32_t cvt_tf32(float a) {
    uint32_t r;
    asm("cvt.rna.tf32.f32 %0, %1;" : "=r"(r) : "f"(a));
    return r;
}

__device__ __forceinline__ void mma_tf32(float* d, const uint32_t* a, const uint32_t* b) {
    asm volatile(
        "mma.sync.aligned.m16n8k8.row.col.f32.tf32.tf32.f32 "
        "{%0,%1,%2,%3}, {%4,%5,%6,%7}, {%8,%9}, {%0,%1,%2,%3};"
        : "+f"(d[0]), "+f"(d[1]), "+f"(d[2]), "+f"(d[3])
        : "r"(a[0]), "r"(a[1]), "r"(a[2]), "r"(a[3]), "r"(b[0]), "r"(b[1]));
}

// ---------------- K0: detect dtype + zero g_cnt / BN accumulators -----------
// Grid-wide zeroing so k_hist can run immediately after (frees launch slot
// ordering: k1 becomes launch #4 = the ncu-profiled launch).
__global__ void k0_zero_detect(const unsigned int* __restrict__ ei_words, int N) {
    int i = blockIdx.x * blockDim.x + threadIdx.x;
    if (i < N) g_cnt[i] = 0;
    if (i < DOUT) { g_sum[i] = 0.f; g_sumsq[i] = 0.f; }
    if (blockIdx.x == 0) {
        __shared__ int any_nz;
        if (threadIdx.x == 0) any_nz = 0;
        __syncthreads();
        int nz = 0;
        for (int t = threadIdx.x; t < 1024; t += blockDim.x)
            nz |= (ei_words[2 * t + 1] != 0u);
        if (nz) atomicOr(&any_nz, 1);
        __syncthreads();
        if (threadIdx.x == 0) g_is64 = any_nz ? 0 : 1;
    }
}

// ---------------- K1: tf32 tensor-core node GEMMs (3xTF32, K-tiled) ---------
// CTA tile M=64 x N=64; K processed in 2 chunks of 64 (smem 51KB -> 4 CTA/SM).
// grid.y: mat = y>>1 (0=Wrel->g_x, 1=Wres->relu->g_res), nhalf = y&1.
// 128 threads, 4 warps, warp tile 16x64. Pitch 68 => conflict-free frag LDS.
#define K1_KT    64
#define K1_PITCH 68
#define K1_SMEM  (3 * 64 * K1_PITCH * 4)   // As + Bh + Bl = 52224 bytes

__global__ __launch_bounds__(128)
void k1_gemm_tf32(const float* __restrict__ feats,
                  const float* __restrict__ Wrel, const float* __restrict__ brel,
                  const float* __restrict__ Wres, const float* __restrict__ bres,
                  int N)
{
    extern __shared__ float smem[];
    float* As = smem;                      // [64][68] fp32
    float* Bh = smem + 64 * K1_PITCH;      // [64][68] tf32 hi
    float* Bl = Bh  + 64 * K1_PITCH;       // [64][68] tf32 lo

    const int tid  = threadIdx.x;
    const int m0   = blockIdx.x * 64;
    const int mat  = blockIdx.y >> 1;
    const int nhalf= blockIdx.y & 1;

    // side job: zero g_ea for later stages (one y-slice only)
    if (blockIdx.y == 1) {
        for (int i = tid; i < 64 * EDIM; i += 128) {
            int n = m0 + (i >> 4);
            if (n < N) g_ea[n * EDIM + (i & 15)] = 0.f;
        }
    }

    const float* Wsel = (mat == 0) ? Wrel : Wres;
    const float* bsel = (mat == 0) ? brel : bres;
    const int nbase = nhalf * 64;

    const int warp = tid >> 5, lane = tid & 31;
    const int g = lane >> 2, tig = lane & 3;
    const int ar0 = warp * 16 + g;

    float d[8][4];
    #pragma unroll
    for (int ns = 0; ns < 8; ns++)
        #pragma unroll
        for (int q = 0; q < 4; q++) d[ns][q] = 0.f;

    for (int kt = 0; kt < DIN / K1_KT; kt++) {
        const int koff = kt * K1_KT;
        __syncthreads();
        // load A tile (64 x 64 fp32), zero-fill OOB rows
        for (int idx = tid; idx < 64 * 16; idx += 128) {
            int row = idx >> 4, c4 = idx & 15;
            int node = m0 + row;
            float4 v = (node < N)
                ? *(const float4*)&feats[(size_t)node * DIN + koff + c4 * 4]
                : make_float4(0.f, 0.f, 0.f, 0.f);
            *(float4*)&As[row * K1_PITCH + c4 * 4] = v;
        }
        // load B tile (64 x 64) and split into tf32 hi/lo
        for (int idx = tid; idx < 64 * 16; idx += 128) {
            int row = idx >> 4, c4 = idx & 15;
            float4 w = *(const float4*)&Wsel[(size_t)(nbase + row) * DIN + koff + c4 * 4];
            float wa[4] = {w.x, w.y, w.z, w.w};
            #pragma unroll
            for (int q = 0; q < 4; q++) {
                uint32_t hb = cvt_tf32(wa[q]);
                float hf = __uint_as_float(hb);
                uint32_t lb = cvt_tf32(wa[q] - hf);
                Bh[row * K1_PITCH + c4 * 4 + q] = __uint_as_float(hb);
                Bl[row * K1_PITCH + c4 * 4 + q] = __uint_as_float(lb);
            }
        }
        __syncthreads();

        #pragma unroll
        for (int ks = 0; ks < K1_KT / 8; ks++) {
            const int k0 = ks * 8;
            float af[4];
            af[0] = As[ar0 * K1_PITCH + k0 + tig];
            af[1] = As[(ar0 + 8) * K1_PITCH + k0 + tig];
            af[2] = As[ar0 * K1_PITCH + k0 + tig + 4];
            af[3] = As[(ar0 + 8) * K1_PITCH + k0 + tig + 4];
            uint32_t ah[4], al[4];
            #pragma unroll
            for (int q = 0; q < 4; q++) {
                ah[q] = cvt_tf32(af[q]);
                al[q] = cvt_tf32(af[q] - __uint_as_float(ah[q]));
            }
            #pragma unroll
            for (int ns = 0; ns < 8; ns++) {
                const int nr = ns * 8 + g;
                uint32_t bh[2], bl[2];
                bh[0] = __float_as_uint(Bh[nr * K1_PITCH + k0 + tig]);
                bh[1] = __float_as_uint(Bh[nr * K1_PITCH + k0 + tig + 4]);
                bl[0] = __float_as_uint(Bl[nr * K1_PITCH + k0 + tig]);
                bl[1] = __float_as_uint(Bl[nr * K1_PITCH + k0 + tig + 4]);
                mma_tf32(d[ns], ah, bh);   // hi*hi
                mma_tf32(d[ns], al, bh);   // lo*hi
                mma_tf32(d[ns], ah, bl);   // hi*lo
            }
        }
    }

    // epilogue: bias, optional relu, store
    float* out = (mat == 0) ? g_x : g_res;
    const int row0 = m0 + warp * 16 + g;
    #pragma unroll
    for (int ns = 0; ns < 8; ns++) {
        const int col = nbase + ns * 8 + tig * 2;
        float b0 = bsel[col], b1 = bsel[col + 1];
        float v0 = d[ns][0] + b0, v1 = d[ns][1] + b1;
        float v2 = d[ns][2] + b0, v3 = d[ns][3] + b1;
        if (mat == 1) {
            v0 = fmaxf(v0, 0.f); v1 = fmaxf(v1, 0.f);
            v2 = fmaxf(v2, 0.f); v3 = fmaxf(v3, 0.f);
        }
        if (row0 < N)
            *(float2*)&out[(size_t)row0 * DOUT + col] = make_float2(v0, v1);
        if (row0 + 8 < N)
            *(float2*)&out[(size_t)(row0 + 8) * DOUT + col] = make_float2(v2, v3);
    }
}

// ---------------- K2a: histogram over dst -------------------------------------
__global__ __launch_bounds__(256)
void k_hist(const void* __restrict__ ei_raw, int E)
{
    int e = blockIdx.x * blockDim.x + threadIdx.x;
    if (e >= E) return;
    int d = g_is64 ? (int)((const long long*)ei_raw)[E + e]
                   : ((const int*)ei_raw)[E + e];
    atomicAdd(&g_cnt[d], 1);
}

// ---------------- K2b: 3-phase multi-block exclusive scan --------------------
__global__ __launch_bounds__(SCAN_BLK)
void k_scan1(int N)
{
    __shared__ int wsum[NWARPS];
    int i = blockIdx.x * SCAN_BLK + threadIdx.x;
    int wid = threadIdx.x >> 5, lane = threadIdx.x & 31;
    int v = (i < N) ? g_cnt[i] : 0;
    #pragma unroll
    for (int o = 16; o > 0; o >>= 1) v += __shfl_down_sync(0xffffffffu, v, o);
    if (lane == 0) wsum[wid] = v;
    __syncthreads();
    if (wid == 0) {
        int s = (lane < NWARPS) ? wsum[lane] : 0;
        #pragma unroll
        for (int o = 16; o > 0; o >>= 1) s += __shfl_down_sync(0xffffffffu, s, o);
        if (lane == 0) g_bsum[blockIdx.x] = s;
    }
}

__global__ __launch_bounds__(MAXB1)
void k_scan2(int nb, int N)
{
    __shared__ int ps[MAXB1];
    int t = threadIdx.x;
    int v = (t < nb) ? g_bsum[t] : 0;
    ps[t] = v;
    __syncthreads();
    #pragma unroll
    for (int o = 1; o < MAXB1; o <<= 1) {
        int y = 0;
        if (t >= o) y = ps[t - o];
        __syncthreads();
        if (t >= o) ps[t] += y;
        __syncthreads();
    }
    if (t < nb) g_boff[t] = ps[t] - v;      // exclusive
    if (t == MAXB1 - 1) g_off[N] = ps[MAXB1 - 1];
}

__global__ __launch_bounds__(SCAN_BLK)
void k_scan3(int N)
{
    __shared__ int wsum[NWARPS];
    int i = blockIdx.x * SCAN_BLK + threadIdx.x;
    int wid = threadIdx.x >> 5, lane = threadIdx.x & 31;
    int v = (i < N) ? g_cnt[i] : 0;
    int x = v;
    #pragma unroll
    for (int o = 1; o < 32; o <<= 1) {
        int y = __shfl_up_sync(0xffffffffu, x, o);
        if (lane >= o) x += y;
    }
    if (lane == 31) wsum[wid] = x;
    __syncthreads();
    if (wid == 0) {
        int s = (lane < NWARPS) ? wsum[lane] : 0;
        #pragma unroll
        for (int o = 1; o < 32; o <<= 1) {
            int y = __shfl_up_sync(0xffffffffu, s, o);
            if (lane >= o) s += y;
        }
        if (lane < NWARPS) wsum[lane] = s;
    }
    __syncthreads();
    int woff = (wid > 0) ? wsum[wid - 1] : 0;
    int excl = x - v + woff + g_boff[blockIdx.x];
    if (i < N) { g_off[i] = excl; g_cur[i] = excl; }
}

// ---------------- K2c: place edges into CSR + scatter edge_attr sums ---------
__global__ __launch_bounds__(256)
void k_place(const void* __restrict__ ei_raw, const float* __restrict__ eattr, int E)
{
    int e = blockIdx.x * blockDim.x + threadIdx.x;
    if (e >= E) return;
    int s, d;
    if (g_is64) {
        const long long* p = (const long long*)ei_raw;
        s = (int)p[e]; d = (int)p[E + e];
    } else {
        const int* p = (const int*)ei_raw;
        s = p[e]; d = p[E + e];
    }
    int pos = atomicAdd(&g_cur[d], 1);
    g_csr_src[pos] = s;

    const float4* a4 = (const float4*)&eattr[(size_t)e * EDIM];
    float* dst = &g_ea[(size_t)d * EDIM];
    red_add_v4(dst + 0,  a4[0]);
    red_add_v4(dst + 4,  a4[1]);
    red_add_v4(dst + 8,  a4[2]);
    red_add_v4(dst + 12, a4[3]);
}

// ---------------- K2d: pull aggregation fused with combine + BN partials ----
__global__ __launch_bounds__(256)
void k_pull(const float* __restrict__ We, const float* __restrict__ be, int N)
{
    __shared__ float s_sum[128];
    __shared__ float s_sq[128];
    int tid = threadIdx.x;
    if (tid < 128) { s_sum[tid] = 0.f; s_sq[tid] = 0.f; }
    __syncthreads();

    int warp = tid >> 5, lane = tid & 31;
    int n = blockIdx.x * 8 + warp;

    if (n < N) {
        const int j0 = g_off[n], j1 = g_off[n + 1];
        const int c0 = lane * 4;

        float4 acc = make_float4(0.f, 0.f, 0.f, 0.f);

        int j = j0;
        for (; j + 3 < j1; j += 4) {
            int s0 = g_csr_src[j],   s1 = g_csr_src[j+1];
            int s2 = g_csr_src[j+2], s3 = g_csr_src[j+3];
            float4 x0 = *(const float4*)&g_x[(size_t)s0 * DOUT + c0];
            float4 x1 = *(const float4*)&g_x[(size_t)s1 * DOUT + c0];
            float4 x2 = *(const float4*)&g_x[(size_t)s2 * DOUT + c0];
            float4 x3 = *(const float4*)&g_x[(size_t)s3 * DOUT + c0];
            acc.x += (x0.x + x1.x) + (x2.x + x3.x);
            acc.y += (x0.y + x1.y) + (x2.y + x3.y);
            acc.z += (x0.z + x1.z) + (x2.z + x3.z);
            acc.w += (x0.w + x1.w) + (x2.w + x3.w);
        }
        for (; j < j1; j++) {
            int s0 = g_csr_src[j];
            float4 x0 = *(const float4*)&g_x[(size_t)s0 * DOUT + c0];
            acc.x += x0.x; acc.y += x0.y; acc.z += x0.z; acc.w += x0.w;
        }

        // per-dst summed edge_attr (coalesced) -> broadcast to all lanes
        float ea = (lane < EDIM) ? g_ea[(size_t)n * EDIM + lane] : 0.f;
        float eav[EDIM];
        #pragma unroll
        for (int q = 0; q < EDIM; q++) eav[q] = __shfl_sync(0xffffffffu, ea, q);

        const float deg = (float)(j1 - j0);
        float4 b = *(const float4*)&be[c0];
        float4 elin = make_float4(b.x * deg, b.y * deg, b.z * deg, b.w * deg);

        const float4* W4 = (const float4*)We;  // row c: 4 float4 chunks
        #pragma unroll
        for (int q4 = 0; q4 < 4; q4++) {
            float4 w0 = W4[(c0 + 0) * 4 + q4];
            float4 w1 = W4[(c0 + 1) * 4 + q4];
            float4 w2 = W4[(c0 + 2) * 4 + q4];
            float4 w3 = W4[(c0 + 3) * 4 + q4];
            float e0v = eav[q4 * 4 + 0], e1v = eav[q4 * 4 + 1];
            float e2v = eav[q4 * 4 + 2], e3v = eav[q4 * 4 + 3];
            elin.x += w0.x * e0v + w0.y * e1v + w0.z * e2v + w0.w * e3v;
            elin.y += w1.x * e0v + w1.y * e1v + w1.z * e2v + w1.w * e3v;
            elin.z += w2.x * e0v + w2.y * e1v + w2.z * e2v + w2.w * e3v;
            elin.w += w3.x * e0v + w3.y * e1v + w3.z * e2v + w3.w * e3v;
        }

        float4 res = *(const float4*)&g_res[(size_t)n * DOUT + c0];
        float4 h;
        h.x = fmaxf(acc.x + elin.x, 0.f) + res.x;
        h.y = fmaxf(acc.y + elin.y, 0.f) + res.y;
        h.z = fmaxf(acc.z + elin.z, 0.f) + res.z;
        h.w = fmaxf(acc.w + elin.w, 0.f) + res.w;
        *(float4*)&g_h[(size_t)n * DOUT + c0] = h;

        atomicAdd(&s_sum[c0 + 0], h.x);
        atomicAdd(&s_sum[c0 + 1], h.y);
        atomicAdd(&s_sum[c0 + 2], h.z);
        atomicAdd(&s_sum[c0 + 3], h.w);
        atomicAdd(&s_sq[c0 + 0], h.x * h.x);
        atomicAdd(&s_sq[c0 + 1], h.y * h.y);
        atomicAdd(&s_sq[c0 + 2], h.z * h.z);
        atomicAdd(&s_sq[c0 + 3], h.w * h.w);
    }

    __syncthreads();
    if (tid < 128) {
        atomicAdd(&g_sum[tid],   s_sum[tid]);
        atomicAdd(&g_sumsq[tid], s_sq[tid]);
    }
}

// ---------------- K4: finalize BN stats --------------------------------------
__global__ void k4_stats(const float* __restrict__ gamma,
                         const float* __restrict__ beta, int N)
{
    int c = threadIdx.x;
    float invN = 1.f / (float)N;
    float mean = g_sum[c] * invN;
    float var  = g_sumsq[c] * invN - mean * mean;
    float rstd = rsqrtf(var + BN_EPS);
    float sc   = gamma[c] * rstd;
    g_scale[c] = sc;
    g_shift[c] = beta[c] - mean * sc;
}

// ---------------- K5: normalize ----------------------------------------------
__global__ __launch_bounds__(256)
void k5_norm(float* __restrict__ out, int total4)
{
    int idx = blockIdx.x * blockDim.x + threadIdx.x;
    if (idx >= total4) return;
    int c4 = (idx & (DOUT / 4 - 1)) * 4;
    float4 h  = *(const float4*)&g_h[idx * 4];
    float4 sc = *(const float4*)&g_scale[c4];
    float4 sh = *(const float4*)&g_shift[c4];
    float4 o;
    o.x = h.x * sc.x + sh.x;
    o.y = h.y * sc.y + sh.y;
    o.z = h.z * sc.z + sh.z;
    o.w = h.w * sc.w + sh.w;
    ((float4*)out)[idx] = o;
}

// ---------------- launch ------------------------------------------------------
extern "C" void kernel_launch(void* const* d_in, const int* in_sizes, int n_in,
                              void* d_out, int out_size)
{
    const float* feats = (const float*)d_in[0];
    const void*  ei    = d_in[1];
    const float* eattr = (const float*)d_in[2];
    const float* Wrel  = (const float*)d_in[3];
    const float* brel  = (const float*)d_in[4];
    const float* We    = (const float*)d_in[5];
    const float* be    = (const float*)d_in[6];
    const float* Wres  = (const float*)d_in[7];
    const float* bres  = (const float*)d_in[8];
    const float* gamma = (const float*)d_in[9];
    const float* beta  = (const float*)d_in[10];

    const int N = in_sizes[0] / DIN;
    const int E = in_sizes[2] / EDIM;
    const int nb = (N + SCAN_BLK - 1) / SCAN_BLK;

    static int smem_set = 0;
    if (!smem_set) {
        cudaFuncSetAttribute(k1_gemm_tf32,
                             cudaFuncAttributeMaxDynamicSharedMemorySize, K1_SMEM);
        smem_set = 1;
    }

    // order chosen so k1_gemm_tf32 is launch #4 (the ncu-profiled launch)
    k0_zero_detect<<<(N + 255) / 256, 256>>>((const unsigned int*)ei, N);
    k_hist<<<(E + 255) / 256, 256>>>(ei, E);
    k_scan1<<<nb, SCAN_BLK>>>(N);
    dim3 g1((N + 63) / 64, 4);
    k1_gemm_tf32<<<g1, 128, K1_SMEM>>>(feats, Wrel, brel, Wres, bres, N);
    k_scan2<<<1, MAXB1>>>(nb, N);
    k_scan3<<<nb, SCAN_BLK>>>(N);
    k_place<<<(E + 255) / 256, 256>>>(ei, eattr, E);
    k_pull<<<(N + 7) / 8, 256>>>(We, be, N);
    k4_stats<<<1, 128>>>(gamma, beta, N);
    int total4 = N * DOUT / 4;
    k5_norm<<<(total4 + 255) / 256, 256>>>((float*)d_out, total4);
}

// round 9
// speedup vs baseline: 1.2586x; 1.0349x over previous
#include <cuda_runtime.h>
#include <cstdint>

#define DIN  128
#define DOUT 128
#define EDIM 16
#define MAXN 50176
#define MAXE 819200
#define BN_EPS 1e-5f
#define SCAN_BLK 512
#define NWARPS (SCAN_BLK / 32)   // 16
#define MAXB1 128                // >= ceil(MAXN/SCAN_BLK) = 98

// ---------------- device scratch (static; no runtime allocation) ------------
__device__ float g_x  [MAXN * DOUT];   // feats @ W_rel^T + b_rel
__device__ float g_res[MAXN * DOUT];   // relu(feats @ W_res^T + b_res)
__device__ float g_h  [MAXN * DOUT];   // pre-BN activations
__device__ float g_ea [MAXN * EDIM];   // scatter-add of edge_attr per dst
__device__ int   g_cnt[MAXN];          // per-dst degree (histogram)
__device__ int   g_off[MAXN + 1];      // CSR offsets
__device__ int   g_cur[MAXN];          // placement cursors
__device__ int   g_csr_src[MAXE];      // src node per CSR slot
__device__ int   g_bsum[MAXB1];        // scan phase-1 block sums
__device__ int   g_boff[MAXB1];        // scan phase-2 block offsets
__device__ float g_sum  [DOUT];
__device__ float g_sumsq[DOUT];
__device__ float g_scale[DOUT];
__device__ float g_shift[DOUT];
__device__ int   g_is64;               // edge_index dtype flag

__device__ __forceinline__ void red_add_v4(float* p, float4 v) {
    asm volatile("red.global.add.v4.f32 [%0], {%1,%2,%3,%4};"
                 :: "l"(p), "f"(v.x), "f"(v.y), "f"(v.z), "f"(v.w)
                 : "memory");
}

__device__ __forceinline__ uint32_t cvt_tf32(float a) {
    uint32_t r;
    asm("cvt.rna.tf32.f32 %0, %1;" : "=r"(r) : "f"(a));
    return r;
}

__device__ __forceinline__ void mma_tf32(float* d, const uint32_t* a, const uint32_t* b) {
    asm volatile(
        "mma.sync.aligned.m16n8k8.row.col.f32.tf32.tf32.f32 "
        "{%0,%1,%2,%3}, {%4,%5,%6,%7}, {%8,%9}, {%0,%1,%2,%3};"
        : "+f"(d[0]), "+f"(d[1]), "+f"(d[2]), "+f"(d[3])
        : "r"(a[0]), "r"(a[1]), "r"(a[2]), "r"(a[3]), "r"(b[0]), "r"(b[1]));
}

// ---------------- K0: detect dtype + zero g_cnt / BN accumulators -----------
__global__ void k0_zero_detect(const unsigned int* __restrict__ ei_words, int N) {
    int i = blockIdx.x * blockDim.x + threadIdx.x;
    if (i < N) g_cnt[i] = 0;
    if (i < DOUT) { g_sum[i] = 0.f; g_sumsq[i] = 0.f; }
    if (blockIdx.x == 0) {
        __shared__ int any_nz;
        if (threadIdx.x == 0) any_nz = 0;
        __syncthreads();
        int nz = 0;
        for (int t = threadIdx.x; t < 1024; t += blockDim.x)
            nz |= (ei_words[2 * t + 1] != 0u);
        if (nz) atomicOr(&any_nz, 1);
        __syncthreads();
        if (threadIdx.x == 0) g_is64 = any_nz ? 0 : 1;
    }
}

// ---------------- K1: tf32 tensor-core node GEMMs (3xTF32, frag-major B) ----
// CTA tile M=128 x N=64, K tiled by 64 (2 chunks). 256 threads = 8 warps,
// warp grid 4(m) x 2(n): warp tile m32 x n32.
// B pre-split hi/lo into FRAGMENT-MAJOR smem: [ks][ns][lane]{bh0,bh1,bl0,bl1}
// -> reader uses one conflict-free LDS.128 per n8-group per k-step.
// grid.y: mat = y>>1 (0=Wrel->g_x, 1=Wres->relu->g_res), nhalf = y&1.
#define K1_KT       64
#define K1_PITCH    68
#define K1_AS_FL    (128 * K1_PITCH)        // 8704 floats
#define K1_BF_FL    (8 * 8 * 32 * 4)        // 8192 floats
#define K1_SMEM     ((K1_AS_FL + K1_BF_FL) * 4)   // 67584 bytes

__global__ __launch_bounds__(256)
void k1_gemm_tf32(const float* __restrict__ feats,
                  const float* __restrict__ Wrel, const float* __restrict__ brel,
                  const float* __restrict__ Wres, const float* __restrict__ bres,
                  int N)
{
    extern __shared__ float smem[];
    float* As = smem;              // [128][68] fp32
    float* Bf = smem + K1_AS_FL;   // frag-major: ((ks*8+ns)*32+lane)*4 + {bh0,bh1,bl0,bl1}

    const int tid   = threadIdx.x;
    const int m0    = blockIdx.x * 128;
    const int mat   = blockIdx.y >> 1;
    const int nhalf = blockIdx.y & 1;

    // side job: zero g_ea for later stages (one y-slice only)
    if (blockIdx.y == 1) {
        for (int i = tid; i < 128 * EDIM; i += 256) {
            int n = m0 + (i >> 4);
            if (n < N) g_ea[n * EDIM + (i & 15)] = 0.f;
        }
    }

    const float* Wsel = (mat == 0) ? Wrel : Wres;
    const float* bsel = (mat == 0) ? brel : bres;
    const int nbase = nhalf * 64;

    const int warp = tid >> 5, lane = tid & 31;
    const int g = lane >> 2, tig = lane & 3;
    const int mwarp = warp >> 1;          // 0..3
    const int nwarp = warp & 1;           // 0..1
    const int am0 = mwarp * 32;           // warp row base within tile

    float d[2][4][4];
    #pragma unroll
    for (int mi = 0; mi < 2; mi++)
        #pragma unroll
        for (int ns = 0; ns < 4; ns++)
            #pragma unroll
            for (int q = 0; q < 4; q++) d[mi][ns][q] = 0.f;

    for (int kt = 0; kt < DIN / K1_KT; kt++) {
        const int koff = kt * K1_KT;
        __syncthreads();
        // A tile: 128 rows x 64 cols fp32, zero-fill OOB rows
        for (int idx = tid; idx < 128 * 16; idx += 256) {
            int row = idx >> 4, c4 = idx & 15;
            int node = m0 + row;
            float4 v = (node < N)
                ? *(const float4*)&feats[(size_t)node * DIN + koff + c4 * 4]
                : make_float4(0.f, 0.f, 0.f, 0.f);
            *(float4*)&As[row * K1_PITCH + c4 * 4] = v;
        }
        // B: one thread per fragment slot -> conflict-free STS.128
        // idx -> ks (0..7), ns (0..7), lane slot (gg,tg)
        for (int idx = tid; idx < 8 * 8 * 32; idx += 256) {
            int ks = idx >> 8;
            int ns = (idx >> 5) & 7;
            int ln = idx & 31;
            int gg = ln >> 2, tg = ln & 3;
            int nrow = nbase + ns * 8 + gg;
            const float* wr = &Wsel[(size_t)nrow * DIN + koff + ks * 8 + tg];
            float w0 = wr[0], w1 = wr[4];
            uint32_t h0 = cvt_tf32(w0);
            uint32_t h1 = cvt_tf32(w1);
            uint32_t l0 = cvt_tf32(w0 - __uint_as_float(h0));
            uint32_t l1 = cvt_tf32(w1 - __uint_as_float(h1));
            float4 fv = make_float4(__uint_as_float(h0), __uint_as_float(h1),
                                    __uint_as_float(l0), __uint_as_float(l1));
            *(float4*)&Bf[(size_t)idx * 4] = fv;
        }
        __syncthreads();

        #pragma unroll
        for (int ks = 0; ks < K1_KT / 8; ks++) {
            const int k0 = ks * 8;
            // A fragments for m32 (2 x m16): rows am0+g(+8,+16,+24)
            float af[8];
            #pragma unroll
            for (int mi = 0; mi < 2; mi++) {
                int r0 = am0 + mi * 16 + g;
                af[mi*4+0] = As[r0 * K1_PITCH + k0 + tig];
                af[mi*4+1] = As[(r0 + 8) * K1_PITCH + k0 + tig];
                af[mi*4+2] = As[r0 * K1_PITCH + k0 + tig + 4];
                af[mi*4+3] = As[(r0 + 8) * K1_PITCH + k0 + tig + 4];
            }
            uint32_t ah[8], al[8];
            #pragma unroll
            for (int q = 0; q < 8; q++) {
                ah[q] = cvt_tf32(af[q]);
                al[q] = cvt_tf32(af[q] - __uint_as_float(ah[q]));
            }
            #pragma unroll
            for (int nsl = 0; nsl < 4; nsl++) {
                const int nsg = nwarp * 4 + nsl;
                float4 b = *(const float4*)&Bf[((ks * 8 + nsg) * 32 + lane) * 4];
                uint32_t bh[2] = {__float_as_uint(b.x), __float_as_uint(b.y)};
                uint32_t bl[2] = {__float_as_uint(b.z), __float_as_uint(b.w)};
                #pragma unroll
                for (int mi = 0; mi < 2; mi++) {
                    mma_tf32(d[mi][nsl], ah + 4*mi, bh);   // hi*hi
                    mma_tf32(d[mi][nsl], al + 4*mi, bh);   // lo*hi
                    mma_tf32(d[mi][nsl], ah + 4*mi, bl);   // hi*lo
                }
            }
        }
    }

    // epilogue: bias, optional relu, store
    float* out = (mat == 0) ? g_x : g_res;
    #pragma unroll
    for (int mi = 0; mi < 2; mi++) {
        const int rA = m0 + am0 + mi * 16 + g;
        #pragma unroll
        for (int nsl = 0; nsl < 4; nsl++) {
            const int col = nbase + (nwarp * 4 + nsl) * 8 + tig * 2;
            float b0 = bsel[col], b1 = bsel[col + 1];
            float v0 = d[mi][nsl][0] + b0, v1 = d[mi][nsl][1] + b1;
            float v2 = d[mi][nsl][2] + b0, v3 = d[mi][nsl][3] + b1;
            if (mat == 1) {
                v0 = fmaxf(v0, 0.f); v1 = fmaxf(v1, 0.f);
                v2 = fmaxf(v2, 0.f); v3 = fmaxf(v3, 0.f);
            }
            if (rA < N)
                *(float2*)&out[(size_t)rA * DOUT + col] = make_float2(v0, v1);
            if (rA + 8 < N)
                *(float2*)&out[(size_t)(rA + 8) * DOUT + col] = make_float2(v2, v3);
        }
    }
}

// ---------------- K2a: histogram over dst -------------------------------------
__global__ __launch_bounds__(256)
void k_hist(const void* __restrict__ ei_raw, int E)
{
    int e = blockIdx.x * blockDim.x + threadIdx.x;
    if (e >= E) return;
    int d = g_is64 ? (int)((const long long*)ei_raw)[E + e]
                   : ((const int*)ei_raw)[E + e];
    atomicAdd(&g_cnt[d], 1);
}

// ---------------- K2b: 3-phase multi-block exclusive scan --------------------
__global__ __launch_bounds__(SCAN_BLK)
void k_scan1(int N)
{
    __shared__ int wsum[NWARPS];
    int i = blockIdx.x * SCAN_BLK + threadIdx.x;
    int wid = threadIdx.x >> 5, lane = threadIdx.x & 31;
    int v = (i < N) ? g_cnt[i] : 0;
    #pragma unroll
    for (int o = 16; o > 0; o >>= 1) v += __shfl_down_sync(0xffffffffu, v, o);
    if (lane == 0) wsum[wid] = v;
    __syncthreads();
    if (wid == 0) {
        int s = (lane < NWARPS) ? wsum[lane] : 0;
        #pragma unroll
        for (int o = 16; o > 0; o >>= 1) s += __shfl_down_sync(0xffffffffu, s, o);
        if (lane == 0) g_bsum[blockIdx.x] = s;
    }
}

__global__ __launch_bounds__(MAXB1)
void k_scan2(int nb, int N)
{
    __shared__ int ps[MAXB1];
    int t = threadIdx.x;
    int v = (t < nb) ? g_bsum[t] : 0;
    ps[t] = v;
    __syncthreads();
    #pragma unroll
    for (int o = 1; o < MAXB1; o <<= 1) {
        int y = 0;
        if (t >= o) y = ps[t - o];
        __syncthreads();
        if (t >= o) ps[t] += y;
        __syncthreads();
    }
    if (t < nb) g_boff[t] = ps[t] - v;      // exclusive
    if (t == MAXB1 - 1) g_off[N] = ps[MAXB1 - 1];
}

__global__ __launch_bounds__(SCAN_BLK)
void k_scan3(int N)
{
    __shared__ int wsum[NWARPS];
    int i = blockIdx.x * SCAN_BLK + threadIdx.x;
    int wid = threadIdx.x >> 5, lane = threadIdx.x & 31;
    int v = (i < N) ? g_cnt[i] : 0;
    int x = v;
    #pragma unroll
    for (int o = 1; o < 32; o <<= 1) {
        int y = __shfl_up_sync(0xffffffffu, x, o);
        if (lane >= o) x += y;
    }
    if (lane == 31) wsum[wid] = x;
    __syncthreads();
    if (wid == 0) {
        int s = (lane < NWARPS) ? wsum[lane] : 0;
        #pragma unroll
        for (int o = 1; o < 32; o <<= 1) {
            int y = __shfl_up_sync(0xffffffffu, s, o);
            if (lane >= o) s += y;
        }
        if (lane < NWARPS) wsum[lane] = s;
    }
    __syncthreads();
    int woff = (wid > 0) ? wsum[wid - 1] : 0;
    int excl = x - v + woff + g_boff[blockIdx.x];
    if (i < N) { g_off[i] = excl; g_cur[i] = excl; }
}

// ---------------- K2c: place edges into CSR + scatter edge_attr sums ---------
__global__ __launch_bounds__(256)
void k_place(const void* __restrict__ ei_raw, const float* __restrict__ eattr, int E)
{
    int e = blockIdx.x * blockDim.x + threadIdx.x;
    if (e >= E) return;
    int s, d;
    if (g_is64) {
        const long long* p = (const long long*)ei_raw;
        s = (int)p[e]; d = (int)p[E + e];
    } else {
        const int* p = (const int*)ei_raw;
        s = p[e]; d = p[E + e];
    }
    int pos = atomicAdd(&g_cur[d], 1);
    g_csr_src[pos] = s;

    const float4* a4 = (const float4*)&eattr[(size_t)e * EDIM];
    float* dst = &g_ea[(size_t)d * EDIM];
    red_add_v4(dst + 0,  a4[0]);
    red_add_v4(dst + 4,  a4[1]);
    red_add_v4(dst + 8,  a4[2]);
    red_add_v4(dst + 12, a4[3]);
}

// ---------------- K2d: pull aggregation fused with combine + BN partials ----
__global__ __launch_bounds__(256)
void k_pull(const float* __restrict__ We, const float* __restrict__ be, int N)
{
    __shared__ float s_sum[128];
    __shared__ float s_sq[128];
    int tid = threadIdx.x;
    if (tid < 128) { s_sum[tid] = 0.f; s_sq[tid] = 0.f; }
    __syncthreads();

    int warp = tid >> 5, lane = tid & 31;
    int n = blockIdx.x * 8 + warp;

    if (n < N) {
        const int j0 = g_off[n], j1 = g_off[n + 1];
        const int c0 = lane * 4;

        float4 acc = make_float4(0.f, 0.f, 0.f, 0.f);

        int j = j0;
        for (; j + 3 < j1; j += 4) {
            int s0 = g_csr_src[j],   s1 = g_csr_src[j+1];
            int s2 = g_csr_src[j+2], s3 = g_csr_src[j+3];
            float4 x0 = *(const float4*)&g_x[(size_t)s0 * DOUT + c0];
            float4 x1 = *(const float4*)&g_x[(size_t)s1 * DOUT + c0];
            float4 x2 = *(const float4*)&g_x[(size_t)s2 * DOUT + c0];
            float4 x3 = *(const float4*)&g_x[(size_t)s3 * DOUT + c0];
            acc.x += (x0.x + x1.x) + (x2.x + x3.x);
            acc.y += (x0.y + x1.y) + (x2.y + x3.y);
            acc.z += (x0.z + x1.z) + (x2.z + x3.z);
            acc.w += (x0.w + x1.w) + (x2.w + x3.w);
        }
        for (; j < j1; j++) {
            int s0 = g_csr_src[j];
            float4 x0 = *(const float4*)&g_x[(size_t)s0 * DOUT + c0];
            acc.x += x0.x; acc.y += x0.y; acc.z += x0.z; acc.w += x0.w;
        }

        // per-dst summed edge_attr (coalesced) -> broadcast to all lanes
        float ea = (lane < EDIM) ? g_ea[(size_t)n * EDIM + lane] : 0.f;
        float eav[EDIM];
        #pragma unroll
        for (int q = 0; q < EDIM; q++) eav[q] = __shfl_sync(0xffffffffu, ea, q);

        const float deg = (float)(j1 - j0);
        float4 b = *(const float4*)&be[c0];
        float4 elin = make_float4(b.x * deg, b.y * deg, b.z * deg, b.w * deg);

        const float4* W4 = (const float4*)We;  // row c: 4 float4 chunks
        #pragma unroll
        for (int q4 = 0; q4 < 4; q4++) {
            float4 w0 = W4[(c0 + 0) * 4 + q4];
            float4 w1 = W4[(c0 + 1) * 4 + q4];
            float4 w2 = W4[(c0 + 2) * 4 + q4];
            float4 w3 = W4[(c0 + 3) * 4 + q4];
            float e0v = eav[q4 * 4 + 0], e1v = eav[q4 * 4 + 1];
            float e2v = eav[q4 * 4 + 2], e3v = eav[q4 * 4 + 3];
            elin.x += w0.x * e0v + w0.y * e1v + w0.z * e2v + w0.w * e3v;
            elin.y += w1.x * e0v + w1.y * e1v + w1.z * e2v + w1.w * e3v;
            elin.z += w2.x * e0v + w2.y * e1v + w2.z * e2v + w2.w * e3v;
            elin.w += w3.x * e0v + w3.y * e1v + w3.z * e2v + w3.w * e3v;
        }

        float4 res = *(const float4*)&g_res[(size_t)n * DOUT + c0];
        float4 h;
        h.x = fmaxf(acc.x + elin.x, 0.f) + res.x;
        h.y = fmaxf(acc.y + elin.y, 0.f) + res.y;
        h.z = fmaxf(acc.z + elin.z, 0.f) + res.z;
        h.w = fmaxf(acc.w + elin.w, 0.f) + res.w;
        *(float4*)&g_h[(size_t)n * DOUT + c0] = h;

        atomicAdd(&s_sum[c0 + 0], h.x);
        atomicAdd(&s_sum[c0 + 1], h.y);
        atomicAdd(&s_sum[c0 + 2], h.z);
        atomicAdd(&s_sum[c0 + 3], h.w);
        atomicAdd(&s_sq[c0 + 0], h.x * h.x);
        atomicAdd(&s_sq[c0 + 1], h.y * h.y);
        atomicAdd(&s_sq[c0 + 2], h.z * h.z);
        atomicAdd(&s_sq[c0 + 3], h.w * h.w);
    }

    __syncthreads();
    if (tid < 128) {
        atomicAdd(&g_sum[tid],   s_sum[tid]);
        atomicAdd(&g_sumsq[tid], s_sq[tid]);
    }
}

// ---------------- K4: finalize BN stats --------------------------------------
__global__ void k4_stats(const float* __restrict__ gamma,
                         const float* __restrict__ beta, int N)
{
    int c = threadIdx.x;
    float invN = 1.f / (float)N;
    float mean = g_sum[c] * invN;
    float var  = g_sumsq[c] * invN - mean * mean;
    float rstd = rsqrtf(var + BN_EPS);
    float sc   = gamma[c] * rstd;
    g_scale[c] = sc;
    g_shift[c] = beta[c] - mean * sc;
}

// ---------------- K5: normalize ----------------------------------------------
__global__ __launch_bounds__(256)
void k5_norm(float* __restrict__ out, int total4)
{
    int idx = blockIdx.x * blockDim.x + threadIdx.x;
    if (idx >= total4) return;
    int c4 = (idx & (DOUT / 4 - 1)) * 4;
    float4 h  = *(const float4*)&g_h[idx * 4];
    float4 sc = *(const float4*)&g_scale[c4];
    float4 sh = *(const float4*)&g_shift[c4];
    float4 o;
    o.x = h.x * sc.x + sh.x;
    o.y = h.y * sc.y + sh.y;
    o.z = h.z * sc.z + sh.z;
    o.w = h.w * sc.w + sh.w;
    ((float4*)out)[idx] = o;
}

// ---------------- launch ------------------------------------------------------
extern "C" void kernel_launch(void* const* d_in, const int* in_sizes, int n_in,
                              void* d_out, int out_size)
{
    const float* feats = (const float*)d_in[0];
    const void*  ei    = d_in[1];
    const float* eattr = (const float*)d_in[2];
    const float* Wrel  = (const float*)d_in[3];
    const float* brel  = (const float*)d_in[4];
    const float* We    = (const float*)d_in[5];
    const float* be    = (const float*)d_in[6];
    const float* Wres  = (const float*)d_in[7];
    const float* bres  = (const float*)d_in[8];
    const float* gamma = (const float*)d_in[9];
    const float* beta  = (const float*)d_in[10];

    const int N = in_sizes[0] / DIN;
    const int E = in_sizes[2] / EDIM;
    const int nb = (N + SCAN_BLK - 1) / SCAN_BLK;

    static int smem_set = 0;
    if (!smem_set) {
        cudaFuncSetAttribute(k1_gemm_tf32,
                             cudaFuncAttributeMaxDynamicSharedMemorySize, K1_SMEM);
        smem_set = 1;
    }

    // order chosen so k1_gemm_tf32 is launch #4 (the ncu-profiled launch)
    k0_zero_detect<<<(N + 255) / 256, 256>>>((const unsigned int*)ei, N);
    k_hist<<<(E + 255) / 256, 256>>>(ei, E);
    k_scan1<<<nb, SCAN_BLK>>>(N);
    dim3 g1((N + 127) / 128, 4);
    k1_gemm_tf32<<<g1, 256, K1_SMEM>>>(feats, Wrel, brel, Wres, bres, N);
    k_scan2<<<1, MAXB1>>>(nb, N);
    k_scan3<<<nb, SCAN_BLK>>>(N);
    k_place<<<(E + 255) / 256, 256>>>(ei, eattr, E);
    k_pull<<<(N + 7) / 8, 256>>>(We, be, N);
    k4_stats<<<1, 128>>>(gamma, beta, N);
    int total4 = N * DOUT / 4;
    k5_norm<<<(total4 + 255) / 256, 256>>>((float*)d_out, total4);
}